// round 17
// baseline (speedup 1.0000x reference)
#include <cuda_runtime.h>
#include <cuda_fp16.h>
#include <math.h>
#include <stdint.h>

#define BB 32
#define SS 2048
#define HH 768
#define EE 2
#define MTOT (BB*SS)
#define LN_EPS 1e-5f

// GEMM: persistent CTAs (296 = 2/SM), tile 128x128, 8 warps of 64x32, BK=64,
// 3-stage cp.async pipeline flowing across tile boundaries, occ=2.
// Single fp16 product (validated rel_err ~3.0e-4, gate 1e-3).
#define BK 64
#define NCHUNK (HH/BK)           // 12
#define OFF_A  0
#define OFF_B  16384
#define STAGE  32768
#define SMEM_TOTAL (3*STAGE)     // 98304 -> 2 CTAs/SM
#define NTILE_N (HH/128)         // 6
#define NTILE   ((MTOT/128)*NTILE_N)  // 3072
#define NCTA    296

// -------- scratch (no allocations allowed) --------
__device__ float g_part[BB*32*HH];
__device__ float g_probs[BB*EE];
__device__ int   g_idx[BB];
__device__ __half g_af[(size_t)MTOT*HH];      // A fp16
__device__ __half g_wt[EE*HH*HH];             // W^T fp16 [e][n][k]

// ---------------------------------------------------------------------------
// helpers
// ---------------------------------------------------------------------------
__device__ __forceinline__ uint32_t smem_u32(const void* p) {
    return (uint32_t)__cvta_generic_to_shared(p);
}
__device__ __forceinline__ void cp16(uint32_t dst, const void* src) {
    asm volatile("cp.async.cg.shared.global [%0], [%1], 16;" :: "r"(dst), "l"(src));
}
#define CP_COMMIT() asm volatile("cp.async.commit_group;" ::: "memory")
#define CP_WAIT0()  asm volatile("cp.async.wait_group 0;" ::: "memory")
#define CP_WAIT1()  asm volatile("cp.async.wait_group 1;" ::: "memory")

__device__ __forceinline__ void ldsm4(uint32_t* r, uint32_t addr) {
    asm volatile("ldmatrix.sync.aligned.m8n8.x4.shared.b16 {%0,%1,%2,%3}, [%4];"
                 : "=r"(r[0]), "=r"(r[1]), "=r"(r[2]), "=r"(r[3]) : "r"(addr));
}
__device__ __forceinline__ void mma16816(float* c, const uint32_t* a, const uint32_t* b) {
    asm volatile(
        "mma.sync.aligned.m16n8k16.row.col.f32.f16.f16.f32 "
        "{%0,%1,%2,%3}, {%4,%5,%6,%7}, {%8,%9}, {%0,%1,%2,%3};"
        : "+f"(c[0]), "+f"(c[1]), "+f"(c[2]), "+f"(c[3])
        : "r"(a[0]), "r"(a[1]), "r"(a[2]), "r"(a[3]), "r"(b[0]), "r"(b[1]));
}
__device__ __forceinline__ uint32_t pack2h(__half a, __half b) {
    return (uint32_t)__half_as_ushort(a) | ((uint32_t)__half_as_ushort(b) << 16);
}

// FMA/ALU-only GELU (tanh approx == sigmoid form): no MUFU in the hot epilogue.
__device__ __forceinline__ float gelu_f(float x) {
    float u = 0.7978845608028654f * x * (1.0f + 0.044715f * x * x);
    float z = 2.885390081777927f * u;                 // 2u*log2(e)
    z = fminf(fmaxf(z, -30.0f), 30.0f);
    float nf = rintf(z);
    float f = z - nf;
    float p = 1.5403530e-4f;
    p = fmaf(p, f, 1.3333558e-3f);
    p = fmaf(p, f, 9.6181291e-3f);
    p = fmaf(p, f, 5.5504109e-2f);
    p = fmaf(p, f, 2.4022651e-1f);
    p = fmaf(p, f, 6.9314718e-1f);
    p = fmaf(p, f, 1.0f);
    float sc = __int_as_float(((int)nf + 127) << 23);
    float e = p * sc;                                 // e^{2u}
    float D = e + 1.0f;
    float r = __int_as_float(0x7EF311C3u - __float_as_int(D));
    r = r * (2.0f - D * r);
    r = r * (2.0f - D * r);
    r = r * (2.0f - D * r);                           // r = 1/(1+e^{2u})
    return x * (1.0f - r);
}

// ---------------------------------------------------------------------------
// 1: fused pool partials + A fp16 convert. grid BB*32, block 192.
//    Unroll x2 with dual accumulators for memory-level parallelism.
// ---------------------------------------------------------------------------
__global__ void pool_split_kernel(const float* __restrict__ in) {
    int blk = blockIdx.x;
    int b = blk >> 5, c = blk & 31;
    int t = threadIdx.x;
    size_t row0 = (size_t)b * SS + (size_t)c * 64;
    const float* base = in + row0 * HH + 4 * t;
    __half* outb = g_af + row0 * HH + 4 * t;
    float4 s0 = {0.f, 0.f, 0.f, 0.f};
    float4 s1 = {0.f, 0.f, 0.f, 0.f};
    #pragma unroll 4
    for (int i = 0; i < 64; i += 2) {
        float4 v0 = *(const float4*)(base + (size_t)i * HH);
        float4 v1 = *(const float4*)(base + (size_t)(i + 1) * HH);
        s0.x += v0.x; s0.y += v0.y; s0.z += v0.z; s0.w += v0.w;
        s1.x += v1.x; s1.y += v1.y; s1.z += v1.z; s1.w += v1.w;
        uint2 h0, h1;
        h0.x = pack2h(__float2half_rn(v0.x), __float2half_rn(v0.y));
        h0.y = pack2h(__float2half_rn(v0.z), __float2half_rn(v0.w));
        h1.x = pack2h(__float2half_rn(v1.x), __float2half_rn(v1.y));
        h1.y = pack2h(__float2half_rn(v1.z), __float2half_rn(v1.w));
        *(uint2*)(outb + (size_t)i * HH) = h0;
        *(uint2*)(outb + (size_t)(i + 1) * HH) = h1;
    }
    float4 s;
    s.x = s0.x + s1.x; s.y = s0.y + s1.y; s.z = s0.z + s1.z; s.w = s0.w + s1.w;
    *(float4*)(g_part + (size_t)blk * HH + 4 * t) = s;
}

// ---------------------------------------------------------------------------
// 2: W[e][k][n] -> W^T fp16 [e][n][k]
// ---------------------------------------------------------------------------
__global__ void convert_w_kernel(const float* __restrict__ W) {
    __shared__ float tile[32][33];
    int e = blockIdx.z;
    int k0 = blockIdx.y * 32, n0 = blockIdx.x * 32;
    int tx = threadIdx.x, ty = threadIdx.y;
    const float* Wp = W + (size_t)e * HH * HH;
    for (int i = ty; i < 32; i += 8)
        tile[i][tx] = Wp[(size_t)(k0 + i) * HH + n0 + tx];
    __syncthreads();
    __half* oh = g_wt + (size_t)e * HH * HH;
    for (int i = ty; i < 32; i += 8)
        oh[(size_t)(n0 + i) * HH + k0 + tx] = __float2half_rn(tile[tx][i]);
}

// ---------------------------------------------------------------------------
// 3: router with fused partial reduction. One block (256 thr) per batch.
// ---------------------------------------------------------------------------
__global__ void router_kernel(const float* __restrict__ gamma,
                              const float* __restrict__ beta,
                              const float* __restrict__ rw,
                              const float* __restrict__ rb) {
    int b = blockIdx.x;
    int t = threadIdx.x;
    __shared__ float red[256];

    float x0 = 0.f, x1 = 0.f, x2 = 0.f;
    #pragma unroll 4
    for (int c = 0; c < 32; c++) {
        const float* p = g_part + (size_t)(b * 32 + c) * HH;
        x0 += p[t]; x1 += p[t + 256]; x2 += p[t + 512];
    }
    x0 *= (1.0f / SS); x1 *= (1.0f / SS); x2 *= (1.0f / SS);

    red[t] = x0 + x1 + x2;
    __syncthreads();
    for (int o = 128; o > 0; o >>= 1) { if (t < o) red[t] += red[t + o]; __syncthreads(); }
    float mu = red[0] * (1.0f / HH);
    __syncthreads();

    float d0 = x0 - mu, d1 = x1 - mu, d2 = x2 - mu;
    red[t] = d0 * d0 + d1 * d1 + d2 * d2;
    __syncthreads();
    for (int o = 128; o > 0; o >>= 1) { if (t < o) red[t] += red[t + o]; __syncthreads(); }
    float rstd = rsqrtf(red[0] * (1.0f / HH) + LN_EPS);
    __syncthreads();

    float n0 = d0 * rstd * gamma[t]       + beta[t];
    float n1 = d1 * rstd * gamma[t + 256] + beta[t + 256];
    float n2 = d2 * rstd * gamma[t + 512] + beta[t + 512];
    float l0 = n0 * rw[t * EE]     + n1 * rw[(t + 256) * EE]     + n2 * rw[(t + 512) * EE];
    float l1 = n0 * rw[t * EE + 1] + n1 * rw[(t + 256) * EE + 1] + n2 * rw[(t + 512) * EE + 1];

    red[t] = l0;
    __syncthreads();
    for (int o = 128; o > 0; o >>= 1) { if (t < o) red[t] += red[t + o]; __syncthreads(); }
    l0 = red[0];
    __syncthreads();
    red[t] = l1;
    __syncthreads();
    for (int o = 128; o > 0; o >>= 1) { if (t < o) red[t] += red[t + o]; __syncthreads(); }

    if (t == 0) {
        l1 = red[0];
        l0 += rb[0];
        l1 += rb[1];
        float m  = fmaxf(l0, l1);
        float e0 = expf(l0 - m);
        float e1 = expf(l1 - m);
        float inv = 1.0f / (e0 + e1);
        g_probs[b * 2 + 0] = e0 * inv;
        g_probs[b * 2 + 1] = e1 * inv;
        g_idx[b] = (l1 > l0) ? 1 : 0;
    }
}

// ---------------------------------------------------------------------------
// 4: persistent GEMM: C = gelu(A @ W_e + b_e).  296 CTAs, 256 thr, occ=2,
//    tiles walked with a continuous 3-stage cp.async pipeline.
// ---------------------------------------------------------------------------
__global__ __launch_bounds__(256, 2) void gemm_tc_kernel(
    const float* __restrict__ bias,
    float* __restrict__ C,
    int do_aux)
{
    extern __shared__ char sm[];
    uint32_t sb = smem_u32(sm);
    int tid = threadIdx.x, lane = tid & 31, wid = tid >> 5;
    int mw = wid & 1;          // 0..1  m-tile of 64
    int nw = wid >> 1;         // 0..3  n-tile of 32

    // ---- hoisted loader addressing (swizzle selector constant per thread) ----
    int r0 = tid >> 3, c0 = tid & 7;
    uint32_t smA = (uint32_t)(OFF_A + r0 * 128 + ((c0 ^ (r0 & 7)) << 4));
    uint32_t smB = (uint32_t)(OFF_B + r0 * 128 + ((c0 ^ (r0 & 7)) << 4));

    // ---- hoisted ldsm addressing ----
    int lx = lane & 7;
    uint32_t arow = (uint32_t)(OFF_A + (mw * 64 + (lane & 15)) * 128);
    uint32_t brow = (uint32_t)(OFF_B + (nw * 32 + (lane & 7) + ((lane & 16) >> 1)) * 128);
    int a_ks = lane >> 4;
    int b_ks = (lane >> 3) & 1;
    uint32_t aoff[4], boff[4];
    #pragma unroll
    for (int ks = 0; ks < 4; ks++) {
        aoff[ks] = arow + (uint32_t)(((ks * 2 + a_ks) ^ lx) << 4);
        boff[ks] = brow + (uint32_t)(((ks * 2 + b_ks) ^ lx) << 4);
    }

    int t0 = blockIdx.x;
    int ntiles = (NTILE - t0 + NCTA - 1) / NCTA;
    int total_chunks = ntiles * NCHUNK;

    // ---- prefetch cursor (leads consumption by 2 chunks) ----
    int pt = t0, pk = 0;
    const __half* pA;
    const __half* pB;
    {
        int pm0 = (pt / NTILE_N) * 128, pn0 = (pt % NTILE_N) * 128;
        int pe = g_idx[pm0 >> 11];
        pA = g_af + (size_t)(pm0 + r0) * HH + c0 * 8;
        pB = g_wt + (size_t)pe * HH * HH + (size_t)(pn0 + r0) * HH + c0 * 8;
    }

    // prologue: issue sequence chunks 0 and 1 (stages 0 and 1)
    #pragma unroll
    for (int q = 0; q < 4; q++) {
        cp16(sb + smA + q * 4096, pA + q * 32 * HH);
        cp16(sb + smB + q * 4096, pB + q * 32 * HH);
    }
    CP_COMMIT();
    #pragma unroll
    for (int q = 0; q < 4; q++) {
        cp16(sb + STAGE + smA + q * 4096, pA + BK + q * 32 * HH);   // FIXED (was +64B off)
        cp16(sb + STAGE + smB + q * 4096, pB + BK + q * 32 * HH);
    }
    CP_COMMIT();
    pk = 2 * BK;   // cursor now at sequence chunk 2 (NCHUNK=12 > 2, no wrap)
    int issued = 2;

    // ---- current (consumed) tile state ----
    int ct = t0;
    int cm0 = (ct / NTILE_N) * 128, cn0 = (ct % NTILE_N) * 128;
    int ce = g_idx[cm0 >> 11];

    float acc[4][4][4];
    #pragma unroll
    for (int mt = 0; mt < 4; mt++)
        #pragma unroll
        for (int nt = 0; nt < 4; nt++)
            #pragma unroll
            for (int q = 0; q < 4; q++) acc[mt][nt][q] = 0.f;

    int cs = 0;
    for (int s = 0; s < total_chunks; s++) {
        uint32_t st = sb + (uint32_t)cs * STAGE;
        if (s < total_chunks - 1) { CP_WAIT1(); } else { CP_WAIT0(); }
        __syncthreads();

        uint32_t stn = sb + (uint32_t)((cs + 2) % 3) * STAGE;
        bool more = (issued < total_chunks);

        #pragma unroll
        for (int ks = 0; ks < 4; ks++) {
            uint32_t a[4][4], b[2][4];
            #pragma unroll
            for (int mt = 0; mt < 4; mt++)
                ldsm4(a[mt], st + aoff[ks] + mt * 2048);
            #pragma unroll
            for (int nt2 = 0; nt2 < 2; nt2++)
                ldsm4(b[nt2], st + boff[ks] + nt2 * 2048);
            if (more) {
                cp16(stn + smA + ks * 4096, pA + pk + ks * 32 * HH);
                cp16(stn + smB + ks * 4096, pB + pk + ks * 32 * HH);
                if (ks == 3) {
                    CP_COMMIT();
                    issued++;
                    pk += BK;
                    if (pk == HH) {
                        pk = 0; pt += NCTA;
                        if (pt < NTILE) {
                            int pm0 = (pt / NTILE_N) * 128, pn0 = (pt % NTILE_N) * 128;
                            int pe = g_idx[pm0 >> 11];
                            pA = g_af + (size_t)(pm0 + r0) * HH + c0 * 8;
                            pB = g_wt + (size_t)pe * HH * HH + (size_t)(pn0 + r0) * HH + c0 * 8;
                        }
                    }
                }
            }
            #pragma unroll
            for (int mt = 0; mt < 4; mt++)
                #pragma unroll
                for (int nt = 0; nt < 4; nt++)
                    mma16816(acc[mt][nt], a[mt], &b[nt >> 1][(nt & 1) * 2]);
        }

        cs = (cs == 2) ? 0 : cs + 1;

        if ((s % NCHUNK) == NCHUNK - 1) {
            // ---- epilogue for tile ct (overlaps with next tile's loads) ----
            int ncol = cn0 + nw * 32;
            const float* bp = bias + ce * HH + ncol + 2 * (lane & 3);
            #pragma unroll
            for (int mt = 0; mt < 4; mt++) {
                int rw0 = cm0 + mw * 64 + mt * 16 + (lane >> 2);
                float* crow0 = C + (size_t)rw0 * HH + ncol + 2 * (lane & 3);
                float* crow1 = crow0 + (size_t)8 * HH;
                #pragma unroll
                for (int nt = 0; nt < 4; nt++) {
                    float2 bv = *(const float2*)(bp + nt * 8);
                    float2 o0, o1;
                    o0.x = gelu_f(acc[mt][nt][0] + bv.x);
                    o0.y = gelu_f(acc[mt][nt][1] + bv.y);
                    o1.x = gelu_f(acc[mt][nt][2] + bv.x);
                    o1.y = gelu_f(acc[mt][nt][3] + bv.y);
                    *(float2*)(crow0 + nt * 8) = o0;
                    *(float2*)(crow1 + nt * 8) = o1;
                }
            }
            #pragma unroll
            for (int mt = 0; mt < 4; mt++)
                #pragma unroll
                for (int nt = 0; nt < 4; nt++)
                    #pragma unroll
                    for (int q = 0; q < 4; q++) acc[mt][nt][q] = 0.f;
            ct += NCTA;
            if (ct < NTILE) {
                cm0 = (ct / NTILE_N) * 128;
                cn0 = (ct % NTILE_N) * 128;
                ce = g_idx[cm0 >> 11];
            }
        }
    }

    // aux loss (CTA 0, one thread). g_probs ready (router ran before GEMM).
    if (do_aux && blockIdx.x == 0 && tid == 0) {
        float a0 = 0.f, a1 = 0.f;
        for (int b2 = 0; b2 < BB; b2++) { a0 += g_probs[2 * b2]; a1 += g_probs[2 * b2 + 1]; }
        a0 *= (1.0f / BB);
        a1 *= (1.0f / BB);
        float d0 = a0 - 0.5f, d1 = a1 - 0.5f;
        C[(size_t)BB * SS * HH] = 0.01f * 0.5f * (d0 * d0 + d1 * d1);
    }
}

// ---------------------------------------------------------------------------
// Launch (GEMM is the profiled 4th launch)
// ---------------------------------------------------------------------------
extern "C" void kernel_launch(void* const* d_in, const int* in_sizes, int n_in,
                              void* d_out, int out_size) {
    const float* inputs   = (const float*)d_in[0];
    const float* ln_gamma = (const float*)d_in[1];
    const float* ln_beta  = (const float*)d_in[2];
    const float* router_w = (const float*)d_in[3];
    const float* router_b = (const float*)d_in[4];
    const float* expert_w = (const float*)d_in[5];
    const float* expert_b = (const float*)d_in[6];
    float* out = (float*)d_out;

    cudaFuncSetAttribute(gemm_tc_kernel,
                         cudaFuncAttributeMaxDynamicSharedMemorySize, SMEM_TOTAL);

    pool_split_kernel<<<BB * 32, 192>>>(inputs);                       // 1
    {
        dim3 g(HH / 32, HH / 32, EE), b(32, 8);
        convert_w_kernel<<<g, b>>>(expert_w);                          // 2
    }
    router_kernel<<<BB, 256>>>(ln_gamma, ln_beta, router_w, router_b); // 3
    int do_aux = (out_size > BB * SS * HH) ? 1 : 0;
    gemm_tc_kernel<<<NCTA, 256, SMEM_TOTAL>>>(expert_b, out, do_aux);  // 4
}